// round 1
// baseline (speedup 1.0000x reference)
#include <cuda_runtime.h>
#include <cstdint>

// Global accumulator for sum of squares (double to make accumulation error a non-issue).
__device__ double g_sumsq;

struct TensorSet {
    const float4* p[5];
    float4*       o[5];   // output slice base (concatenated layout), vec4 units
    long          n[5];   // vec4 element counts
};

__global__ void zero_accum_kernel() {
    g_sumsq = 0.0;
}

__global__ void __launch_bounds__(256) reduce_sumsq_kernel(TensorSet ts) {
    float acc = 0.0f;
    const long stride = (long)gridDim.x * blockDim.x;
    const long base = (long)blockIdx.x * blockDim.x + threadIdx.x;

    #pragma unroll
    for (int t = 0; t < 5; ++t) {
        const float4* __restrict__ p = ts.p[t];
        const long n = ts.n[t];
        for (long i = base; i < n; i += stride) {
            float4 v = p[i];
            acc = fmaf(v.x, v.x, acc);
            acc = fmaf(v.y, v.y, acc);
            acc = fmaf(v.z, v.z, acc);
            acc = fmaf(v.w, v.w, acc);
        }
    }

    // warp reduce
    #pragma unroll
    for (int off = 16; off > 0; off >>= 1)
        acc += __shfl_xor_sync(0xFFFFFFFFu, acc, off);

    __shared__ float warp_sums[8];
    const int lane = threadIdx.x & 31;
    const int wid  = threadIdx.x >> 5;
    if (lane == 0) warp_sums[wid] = acc;
    __syncthreads();

    if (wid == 0) {
        float s = (lane < (blockDim.x >> 5)) ? warp_sums[lane] : 0.0f;
        #pragma unroll
        for (int off = 4; off > 0; off >>= 1)
            s += __shfl_xor_sync(0xFFFFFFFFu, s, off);
        if (lane == 0)
            atomicAdd(&g_sumsq, (double)s);
    }
}

__global__ void __launch_bounds__(256) scale_kernel(TensorSet ts) {
    const float norm = sqrtf((float)g_sumsq);
    const float scale = (norm > 1.0f) ? (1.0f / (norm + 1e-6f)) : 1.0f;

    const long stride = (long)gridDim.x * blockDim.x;
    const long base = (long)blockIdx.x * blockDim.x + threadIdx.x;

    #pragma unroll
    for (int t = 0; t < 5; ++t) {
        const float4* __restrict__ p = ts.p[t];
        float4* __restrict__ o = ts.o[t];
        const long n = ts.n[t];
        for (long i = base; i < n; i += stride) {
            float4 v = p[i];
            v.x *= scale; v.y *= scale; v.z *= scale; v.w *= scale;
            o[i] = v;
        }
    }
}

extern "C" void kernel_launch(void* const* d_in, const int* in_sizes, int n_in,
                              void* d_out, int out_size) {
    TensorSet ts;
    long off = 0;
    float* out = (float*)d_out;
    for (int t = 0; t < 5; ++t) {
        ts.p[t] = (const float4*)d_in[t];
        ts.o[t] = (float4*)(out + off);
        ts.n[t] = (long)in_sizes[t] / 4;   // all counts divisible by 4
        off += (long)in_sizes[t];
    }

    zero_accum_kernel<<<1, 1>>>();
    reduce_sumsq_kernel<<<2048, 256>>>(ts);
    scale_kernel<<<2048, 256>>>(ts);
}